// round 1
// baseline (speedup 1.0000x reference)
#include <cuda_runtime.h>
#include <cuda_bf16.h>

// DisplaceChannel: per-group bilinear shift.
// inp:    (B=16, C=256, H=128, W=128) fp32
// offset: (G=32, 2) fp32 ; dx = offset[g][0]*128, dy = offset[g][1]*128
// out[b,c,y,x] = sum over 4 taps w_t * inp[b,c, y+iy+ty, x+ix+tx] (zero outside bounds)
// where iy=floor(dy), ix=floor(dx), fy=dy-iy, fx=dx-ix, group g = c/8.

#define H 128
#define W 128
#define C 256
#define GROUPS 32
#define BIND_CHAN 8

__global__ __launch_bounds__(256) void displace_kernel(
    const float* __restrict__ inp,
    const float* __restrict__ offset,
    float* __restrict__ out)
{
    // Each thread produces 4 consecutive x outputs (float4 store).
    // Thread index decomposition:
    //   bits [0:5)  -> x-quad (32 quads of 4 = 128 x)
    //   bits [5:12) -> y (128)
    //   bits [12:)  -> plane = b*C + c (4096 planes)
    int t = blockIdx.x * blockDim.x + threadIdx.x;
    int x4    = (t & 31) << 2;       // 0,4,...,124
    int y     = (t >> 5) & 127;
    int plane = t >> 12;             // 0 .. 4095
    int c     = plane & (C - 1);
    int g     = c >> 3;              // c / BIND_CHAN

    // Per-group displacement (L1-resident tiny table; recompute per thread).
    float dx = __ldg(offset + 2 * g)     * 128.0f;
    float dy = __ldg(offset + 2 * g + 1) * 128.0f;
    float x0f = floorf(dx);
    float y0f = floorf(dy);
    float fx = dx - x0f;
    float fy = dy - y0f;
    int ix = (int)x0f;
    int iy = (int)y0f;

    float w00 = (1.0f - fy) * (1.0f - fx);
    float w01 = (1.0f - fy) * fx;
    float w10 = fy * (1.0f - fx);
    float w11 = fy * fx;

    const float* base = inp + (size_t)plane * (H * W);
    int ys0 = y + iy;
    int ys1 = ys0 + 1;
    bool vy0 = ((unsigned)ys0) < (unsigned)H;
    bool vy1 = ((unsigned)ys1) < (unsigned)H;
    const float* row0 = base + ys0 * W;
    const float* row1 = base + ys1 * W;

    // Tap window: columns x4+ix .. x4+ix+4 (5 wide) over 2 rows.
    float r0[5], r1[5];
#pragma unroll
    for (int j = 0; j < 5; j++) {
        int xs = x4 + ix + j;
        bool vx = ((unsigned)xs) < (unsigned)W;
        r0[j] = (vy0 && vx) ? __ldg(row0 + xs) : 0.0f;
        r1[j] = (vy1 && vx) ? __ldg(row1 + xs) : 0.0f;
    }

    float4 o;
    o.x = w00 * r0[0] + w01 * r0[1] + w10 * r1[0] + w11 * r1[1];
    o.y = w00 * r0[1] + w01 * r0[2] + w10 * r1[1] + w11 * r1[2];
    o.z = w00 * r0[2] + w01 * r0[3] + w10 * r1[2] + w11 * r1[3];
    o.w = w00 * r0[3] + w01 * r0[4] + w10 * r1[3] + w11 * r1[4];

    float4* outp = (float4*)(out + (size_t)plane * (H * W) + y * W + x4);
    *outp = o;
}

extern "C" void kernel_launch(void* const* d_in, const int* in_sizes, int n_in,
                              void* d_out, int out_size)
{
    const float* inp    = (const float*)d_in[0];
    const float* offset = (const float*)d_in[1];
    float* out = (float*)d_out;

    // total threads = out_size / 4 = 16,777,216
    int threads = 256;
    int total = out_size / 4;
    int blocks = (total + threads - 1) / threads;  // 65536
    displace_kernel<<<blocks, threads>>>(inp, offset, out);
}

// round 2
// speedup vs baseline: 1.1703x; 1.1703x over previous
#include <cuda_runtime.h>
#include <cuda_bf16.h>

// DisplaceChannel: per-group bilinear shift.
// inp:    (B=16, C=256, H=128, W=128) fp32
// offset: (G=32, 2) fp32 ; dx = offset[g][0]*128, dy = offset[g][1]*128
// out[b,c,y,x] = w00*in[y+iy,x+ix] + w01*in[y+iy,x+ix+1]
//              + w10*in[y+iy+1,x+ix] + w11*in[y+iy+1,x+ix+1]   (taps zero OOB)
// group g = c/8 -> warp-uniform shift; misalignment r = ix&3 is warp-uniform.

#define H 128
#define W 128
#define C 256

// Emit 8 outputs from two 12-float chunk rows with compile-time shift R.
template<int R>
__device__ __forceinline__ void emit8(const float* __restrict__ ca,
                                      const float* __restrict__ cb,
                                      float w00, float w01, float w10, float w11,
                                      float4* __restrict__ outp)
{
    float o[8];
#pragma unroll
    for (int k = 0; k < 8; k++) {
        o[k] = w00 * ca[R + k] + w01 * ca[R + k + 1]
             + w10 * cb[R + k] + w11 * cb[R + k + 1];
    }
    float4 o0 = make_float4(o[0], o[1], o[2], o[3]);
    float4 o1 = make_float4(o[4], o[5], o[6], o[7]);
    outp[0] = o0;
    outp[1] = o1;
}

__global__ __launch_bounds__(256) void displace_kernel(
    const float* __restrict__ inp,
    const float* __restrict__ offset,
    float* __restrict__ out)
{
    // 8 outputs per thread.
    //   bits [0:4)  -> x-oct (16 octs of 8 = 128 x)
    //   bits [4:11) -> y (128)
    //   bits [11:)  -> plane = b*C + c (4096 planes)
    int t = blockIdx.x * blockDim.x + threadIdx.x;
    int x8    = (t & 15) << 3;       // 0,8,...,120
    int y     = (t >> 4) & 127;
    int plane = t >> 11;
    int c     = plane & (C - 1);
    int g     = c >> 3;

    float dx = __ldg(offset + 2 * g)     * 128.0f;
    float dy = __ldg(offset + 2 * g + 1) * 128.0f;
    float x0f = floorf(dx);
    float y0f = floorf(dy);
    float fx = dx - x0f;
    float fy = dy - y0f;
    int ix = (int)x0f;
    int iy = (int)y0f;

    float w00 = (1.0f - fy) * (1.0f - fx);
    float w01 = (1.0f - fy) * fx;
    float w10 = fy * (1.0f - fx);
    float w11 = fy * fx;

    int r  = ix & 3;                 // warp-uniform misalignment
    int a0 = x8 + ix - r;            // 4-aligned base of the 12-float window

    const float* base = inp + (size_t)plane * (H * W);
    int ys0 = y + iy;
    int ys1 = ys0 + 1;
    bool vy0 = ((unsigned)ys0) < (unsigned)H;
    bool vy1 = ((unsigned)ys1) < (unsigned)H;
    const float* row0 = base + ys0 * W;
    const float* row1 = base + ys1 * W;

    // Load three aligned float4 chunks per row; zero if chunk is OOB.
    // Chunks are 4-aligned and W is a multiple of 4, so element validity
    // == chunk validity.
    float ca[12], cb[12];
#pragma unroll
    for (int ch = 0; ch < 3; ch++) {
        int p = a0 + 4 * ch;
        bool vp = (p >= 0) && (p <= W - 4);
        float4 va = (vy0 && vp) ? *(const float4*)(row0 + p) : make_float4(0.f, 0.f, 0.f, 0.f);
        float4 vb = (vy1 && vp) ? *(const float4*)(row1 + p) : make_float4(0.f, 0.f, 0.f, 0.f);
        ca[4*ch+0] = va.x; ca[4*ch+1] = va.y; ca[4*ch+2] = va.z; ca[4*ch+3] = va.w;
        cb[4*ch+0] = vb.x; cb[4*ch+1] = vb.y; cb[4*ch+2] = vb.z; cb[4*ch+3] = vb.w;
    }

    float4* outp = (float4*)(out + (size_t)plane * (H * W) + y * W + x8);

    // r is warp-uniform -> uniform branch, no divergence.
    switch (r) {
        case 0: emit8<0>(ca, cb, w00, w01, w10, w11, outp); break;
        case 1: emit8<1>(ca, cb, w00, w01, w10, w11, outp); break;
        case 2: emit8<2>(ca, cb, w00, w01, w10, w11, outp); break;
        default: emit8<3>(ca, cb, w00, w01, w10, w11, outp); break;
    }
}

extern "C" void kernel_launch(void* const* d_in, const int* in_sizes, int n_in,
                              void* d_out, int out_size)
{
    const float* inp    = (const float*)d_in[0];
    const float* offset = (const float*)d_in[1];
    float* out = (float*)d_out;

    int threads = 256;
    int total = out_size / 8;                    // 8,388,608 threads
    int blocks = (total + threads - 1) / threads; // 32768
    displace_kernel<<<blocks, threads>>>(inp, offset, out);
}